// round 5
// baseline (speedup 1.0000x reference)
#include <cuda_runtime.h>

// PCN_28681791603104 — reduced computation (R0 analysis, verified rel_err ~1e-7):
//   out[0:4096] = initial S[14]
//   out[4096:]  = Wg after 10 cycles of the self-contained layer-13 recurrence:
//       P13 = relu(S14) @ Wk13^T (constant)
//       E = S13 - P13 ; G = Wg^T @ E ; S13 += LR*(relu'(S13)-E)*G ; Wg' = LR*E*relu'(S14)^T
//
// R4: approach the single-SM FMA floor (~22.5K cyc):
//   - one __syncthreads per cycle (E x2 buffers, Wg x3 buffers, rotating ptrs)
//   - lane tile 4x4 (warp 16x16), split-K by half-warp + shfl_xor(16):
//     per k-iter: 1 LDS.128 A (rows pre-paired for f32x2) + 1 LDS.128 B
//     + 4 packs + 8 FFMA2
//   - all 32 lanes store (2 STS.128/matrix), last-cycle Wg straight to gmem

#define LRV 0.01f
#define NCYC 10
#define STR 68
#define ARR (64 * STR)
#define SMEM_FLOATS (7 * ARR)   // sA, sB, sE0, sE1, sW0, sW1, sW2

__device__ __forceinline__ unsigned long long pack2(float x) {
    unsigned long long r;
    asm("mov.b64 %0, {%1, %1};" : "=l"(r) : "f"(x));
    return r;
}
__device__ __forceinline__ void fma2(unsigned long long& a,
                                     unsigned long long b, unsigned long long c) {
    asm("fma.rn.f32x2 %0, %1, %2, %0;" : "+l"(a) : "l"(b), "l"(c));
}
__device__ __forceinline__ void add2(unsigned long long& a, unsigned long long b) {
    asm("add.rn.f32x2 %0, %0, %1;" : "+l"(a) : "l"(b));
}
__device__ __forceinline__ float2 up2(unsigned long long v) {
    float2 f;
    asm("mov.b64 {%0, %1}, %2;" : "=f"(f.x), "=f"(f.y) : "l"(v));
    return f;
}

extern __shared__ float smp[];

// out[a][b] = sum_k A[k][a] * B[k][b].
// A = sX + kh*STR + A0 (4 consecutive a, as 2 f32x2 row-pairs), B likewise 4 b.
// Half-warp kh handles k = 2*jj + kh; shfl_xor(16) combines.
// g[q], q = rp*4 + j: rows (A0+2rp, A0+2rp+1) packed in (x,y), col B0+j.
__device__ __forceinline__ void gemm64(const float* __restrict__ A,
                                       const float* __restrict__ B,
                                       float2 g[8]) {
    unsigned long long acc[8] = {0, 0, 0, 0, 0, 0, 0, 0};
    #pragma unroll
    for (int jj = 0; jj < 32; jj++) {
        ulonglong2 ap = *(const ulonglong2*)(A + jj * 2 * STR);
        float4 bv = *(const float4*)(B + jj * 2 * STR);
        unsigned long long b0 = pack2(bv.x), b1 = pack2(bv.y),
                           b2 = pack2(bv.z), b3 = pack2(bv.w);
        fma2(acc[0], ap.x, b0); fma2(acc[1], ap.x, b1);
        fma2(acc[2], ap.x, b2); fma2(acc[3], ap.x, b3);
        fma2(acc[4], ap.y, b0); fma2(acc[5], ap.y, b1);
        fma2(acc[6], ap.y, b2); fma2(acc[7], ap.y, b3);
    }
    #pragma unroll
    for (int i = 0; i < 8; i++) {
        unsigned long long o = __shfl_xor_sync(0xFFFFFFFFu, acc[i], 16);
        add2(acc[i], o);
        g[i] = up2(acc[i]);
    }
}

__global__ void __launch_bounds__(512, 1) pcn_kernel(
    const float* __restrict__ S,    // (15,64,64)
    const float* __restrict__ Wk,   // (14,64,64)
    const float* __restrict__ Wg0,  // (64,64)
    float* __restrict__ out,
    int wg_off)
{
    float* sA  = smp;               // relu(S14)^T : [i*STR + a]
    float* sB  = smp + ARR;         // Wk13^T      : [i*STR + b]
    float* sE0 = smp + 2 * ARR;
    float* sE1 = smp + 3 * ARR;
    float* sW0 = smp + 4 * ARR;
    float* sW1 = smp + 5 * ARR;
    float* sW2 = smp + 6 * ARR;

    const float* __restrict__ S13g  = S  + 13 * 4096;
    const float* __restrict__ S14g  = S  + 14 * 4096;
    const float* __restrict__ Wk13g = Wk + 13 * 4096;

    const int t  = threadIdx.x;
    const int w  = t >> 5, l = t & 31;
    const int wr = w >> 2, wc = w & 3;
    const int kh = l >> 4;
    const int lr = (l >> 2) & 3, lc = l & 3;
    const int A0 = wr * 16 + lr * 4;       // lane's 4 output rows
    const int B0 = wc * 16 + lc * 4;       // lane's 4 output cols

    // ---- Prologue ----
    #pragma unroll
    for (int kk = 0; kk < 8; kk++) {
        int k = t + kk * 512;
        int rr = k >> 6, cc = k & 63;
        float v = S14g[k];
        out[k] = v;                         // out[0:4096] = initial S[14]
        sA[cc * STR + rr] = fmaxf(v, 0.0f);
        sB[cc * STR + rr] = Wk13g[k];
        sW0[rr * STR + cc] = Wg0[k];        // Wg_0, read by GEMM of cycle 0
    }

    // Packed state: q = rp*4 + j -> rows (A0+2rp, A0+2rp+1), col B0+j
    float2 s13p[8];
    unsigned mbits = 0;                     // LR-mask bits: bit (2q + comp)
    #pragma unroll
    for (int rp = 0; rp < 2; rp++)
        #pragma unroll
        for (int j = 0; j < 4; j++) {
            int q = rp * 4 + j, c = B0 + j, r = A0 + 2 * rp;
            s13p[q].x = S13g[r * 64 + c];
            s13p[q].y = S13g[(r + 1) * 64 + c];
            if (S14g[c * 64 + r]     > 0.0f) mbits |= 1u << (2 * q);
            if (S14g[c * 64 + r + 1] > 0.0f) mbits |= 1u << (2 * q + 1);
        }
    __syncthreads();

    // ---- P13 (constant) ----
    float2 p13[8];
    gemm64(sA + kh * STR + A0, sB + kh * STR + B0, p13);

    // ---- 10 PCN cycles, one barrier each ----
    float* pe0 = sE0, * pe1 = sE1;               // store+read pe0, then swap
    float* pw0 = sW0, * pw1 = sW1, * pw2 = sW2;  // read pw0, store pw1, rotate
    const int rs = A0 + 2 * kh;                  // rows this lane stores
    const int qb = kh * 4;

    #pragma unroll 1
    for (int cyc = 0; cyc < NCYC; cyc++) {
        // E = S13 - P13 ; publish this lane's 2 rows
        float2 e[8];
        #pragma unroll
        for (int q = 0; q < 8; q++) {
            e[q].x = s13p[q].x - p13[q].x;
            e[q].y = s13p[q].y - p13[q].y;
        }
        *(float4*)(pe0 + rs * STR + B0) =
            make_float4(e[qb + 0].x, e[qb + 1].x, e[qb + 2].x, e[qb + 3].x);
        *(float4*)(pe0 + (rs + 1) * STR + B0) =
            make_float4(e[qb + 0].y, e[qb + 1].y, e[qb + 2].y, e[qb + 3].y);

        __syncthreads();   // E_t (all warps) + Wg_t (stored last cycle) visible

        // G = Wg_t^T @ E_t
        float2 g[8];
        gemm64(pw0 + kh * STR + A0, pe0 + kh * STR + B0, g);

        // S13 += LR*(relu'(S13) - E)*G ;  Wg_{t+1} = LR * E * mask
        float2 wgr[8];
        #pragma unroll
        for (int q = 0; q < 8; q++) {
            float rx = (s13p[q].x > 0.0f) ? 1.0f : 0.0f;
            float ry = (s13p[q].y > 0.0f) ? 1.0f : 0.0f;
            s13p[q].x = fmaf(LRV * (rx - e[q].x), g[q].x, s13p[q].x);
            s13p[q].y = fmaf(LRV * (ry - e[q].y), g[q].y, s13p[q].y);
            wgr[q].x = (mbits >> (2 * q)     & 1u) ? e[q].x * LRV : 0.0f;
            wgr[q].y = (mbits >> (2 * q + 1) & 1u) ? e[q].y * LRV : 0.0f;
        }

        if (cyc < NCYC - 1) {
            // store Wg_{t+1}; safe: this point is after BAR_t > all GEMM_{t-2}
            // reads of pw1's previous contents
            *(float4*)(pw1 + rs * STR + B0) =
                make_float4(wgr[qb + 0].x, wgr[qb + 1].x, wgr[qb + 2].x, wgr[qb + 3].x);
            *(float4*)(pw1 + (rs + 1) * STR + B0) =
                make_float4(wgr[qb + 0].y, wgr[qb + 1].y, wgr[qb + 2].y, wgr[qb + 3].y);
        } else if (wg_off >= 0) {
            // final Wg straight to gmem
            *(float4*)(out + wg_off + rs * 64 + B0) =
                make_float4(wgr[qb + 0].x, wgr[qb + 1].x, wgr[qb + 2].x, wgr[qb + 3].x);
            *(float4*)(out + wg_off + (rs + 1) * 64 + B0) =
                make_float4(wgr[qb + 0].y, wgr[qb + 1].y, wgr[qb + 2].y, wgr[qb + 3].y);
        }

        // rotate buffers
        float* te = pe0; pe0 = pe1; pe1 = te;
        float* tw = pw0; pw0 = pw1; pw1 = pw2; pw2 = tw;
    }
}

extern "C" void kernel_launch(void* const* d_in, const int* in_sizes, int n_in,
                              void* d_out, int out_size) {
    // Identify inputs by element count: S 61440, Wk 57344, Wg 4096.
    const float* S  = nullptr;
    const float* Wk = nullptr;
    const float* Wg = nullptr;
    for (int i = 0; i < n_in; i++) {
        if (in_sizes[i] == 61440)      S  = (const float*)d_in[i];
        else if (in_sizes[i] == 57344) Wk = (const float*)d_in[i];
        else if (in_sizes[i] == 4096)  Wg = (const float*)d_in[i];
    }

    cudaFuncSetAttribute(pcn_kernel,
                         cudaFuncAttributeMaxDynamicSharedMemorySize,
                         SMEM_FLOATS * (int)sizeof(float));

    int wg_off = (out_size >= 8192) ? 4096 : -1;
    pcn_kernel<<<1, 512, SMEM_FLOATS * (int)sizeof(float)>>>(
        S, Wk, Wg, (float*)d_out, wg_off);
}